// round 1
// baseline (speedup 1.0000x reference)
#include <cuda_runtime.h>
#include <math.h>

#define EPSC 1e-6f
#define INV_SQRT_2PI 0.3989422804014327f

__constant__ float GT[10] = {0.715951561820333f, 1.039358092507381f, 0.948607106485449f,
                             0.715951555650637f, 0.715951343627955f, 1.039354251532628f,
                             0.484068718800797f, 0.715951452277779f, 1.039355768740833f,
                             1.446433070133343f};
__constant__ float GS[10] = {0.519483084417772f, 0.357944855434941f, 0.723301195883257f,
                             0.474918009444542f, 0.519483382721337f, 0.357945091498072f,
                             0.519481351904163f, 0.357945544542554f, 0.242049896394596f,
                             0.357944917042638f};

// ------------------- scratch (__device__ globals, no allocs) -------------------
__device__ float g_h1[64 * 512];
__device__ float g_zvar[64 * 64];
__device__ float g_m3[64 * 512];
__device__ float g_a0[64 * 512];
__device__ float g_a1[64 * 512];
__device__ float g_a2[64 * 512];
__device__ float g_a3[64 * 512];
__device__ float g_v[64 * 512];
__device__ float g_H[(size_t)64 * 512 * 512];   // cov_h3, 67 MB
__device__ float g_m41[64 * 784];
__device__ float g_diag41[64 * 784];

// ------------------- generic small GEMM: out[64,N] = act(A[64,K] @ Bw[N,K]^T + bias) ----
// MODE 0: tanh    MODE 1: identity    MODE 2: identity -> out, exp(val) -> out2
template <int MODE>
__global__ __launch_bounds__(256) void gemm_bias_act(
    const float* __restrict__ A, const float* __restrict__ Bw,
    const float* __restrict__ bias, float* __restrict__ out,
    int N, int K, float* __restrict__ out2)
{
    __shared__ float As[16 * 68];
    __shared__ float Bs[16 * 68];
    const int t = threadIdx.x;
    const int tx = t & 15, ty = t >> 4;
    const int n_base = blockIdx.x * 64;

    float acc[4][4];
#pragma unroll
    for (int r = 0; r < 4; r++)
#pragma unroll
        for (int c = 0; c < 4; c++) acc[r][c] = 0.f;

    for (int k0 = 0; k0 < K; k0 += 16) {
        {   // A tile (64 rows x 16 k), transposed into As[k][m]
            int row = t >> 2, c4 = t & 3;
            float4 v = *reinterpret_cast<const float4*>(A + (size_t)row * K + k0 + c4 * 4);
            As[(c4 * 4 + 0) * 68 + row] = v.x;
            As[(c4 * 4 + 1) * 68 + row] = v.y;
            As[(c4 * 4 + 2) * 68 + row] = v.z;
            As[(c4 * 4 + 3) * 68 + row] = v.w;
        }
        {   // B tile (64 n-rows x 16 k), transposed into Bs[k][n]
            int row = t >> 2, c4 = t & 3;
            int ng = n_base + row;
            float4 v = make_float4(0.f, 0.f, 0.f, 0.f);
            if (ng < N) v = *reinterpret_cast<const float4*>(Bw + (size_t)ng * K + k0 + c4 * 4);
            Bs[(c4 * 4 + 0) * 68 + row] = v.x;
            Bs[(c4 * 4 + 1) * 68 + row] = v.y;
            Bs[(c4 * 4 + 2) * 68 + row] = v.z;
            Bs[(c4 * 4 + 3) * 68 + row] = v.w;
        }
        __syncthreads();
#pragma unroll
        for (int kk = 0; kk < 16; kk++) {
            float4 am = *reinterpret_cast<const float4*>(&As[kk * 68 + ty * 4]);
            float4 bn = *reinterpret_cast<const float4*>(&Bs[kk * 68 + tx * 4]);
            float a[4] = {am.x, am.y, am.z, am.w};
            float bb[4] = {bn.x, bn.y, bn.z, bn.w};
#pragma unroll
            for (int r = 0; r < 4; r++)
#pragma unroll
                for (int c = 0; c < 4; c++) acc[r][c] += a[r] * bb[c];
        }
        __syncthreads();
    }

#pragma unroll
    for (int r = 0; r < 4; r++) {
        int m = ty * 4 + r;
#pragma unroll
        for (int c = 0; c < 4; c++) {
            int ng = n_base + tx * 4 + c;
            if (ng < N) {
                float val = acc[r][c] + bias[ng];
                if (MODE == 0) val = tanhf(val);
                out[(size_t)m * N + ng] = val;
                if (MODE == 2) out2[(size_t)m * N + ng] = expf(val);
            }
        }
    }
}

// ------------------- moments (tanh): A0..A3 coefficients + clipped diag --------
__global__ void moments_tanh(const float* __restrict__ w3)
{
    int idx = blockIdx.x * blockDim.x + threadIdx.x;
    if (idx >= 64 * 512) return;
    int b = idx >> 9, i = idx & 511;

    const float* wr = w3 + i * 64;
    const float* zr = g_zvar + b * 64;
    float v = 0.f;
#pragma unroll 8
    for (int l = 0; l < 64; l++) v += wr[l] * wr[l] * zr[l];
    v = fmaxf(v, EPSC);

    float m = g_m3[idx];
    float s0 = 0.f, s1 = 0.f, s2 = 0.f, s3 = 0.f;
#pragma unroll
    for (int g = 0; g < 10; g++) {
        float gam = GT[g];
        float cg = 1.0f / (2.0f * gam * gam);
        float ivh = v + cg;
        float sq = sqrtf(ivh);
        float mu = m / sq;
        float Bv = expf(-0.5f * mu * mu) * INV_SQRT_2PI / sq;
        float Cv = 0.5f * (1.0f + erff(mu * 0.70710678118654752f));
        s0 += 2.f * Cv - 1.f;
        s1 += 2.f * Bv;
        s2 += -Bv * m / ivh;
        s3 += (1.f / 3.f) * Bv * (m * m - ivh) / (ivh * ivh);
    }
    g_a0[idx] = s0 * 0.1f;
    g_a1[idx] = s1 * 0.1f;
    g_a2[idx] = s2 * 0.1f;
    g_a3[idx] = s3 * 0.1f;
    g_v[idx]  = v;
}

// ------------------- build H = cov_h3 (fused cov3 + moment transform) ----------
// C[b,i,j] = sum_l w3[i,l] * (w3[j,l] * zvar[b,l]) ; then elementwise transform.
__global__ __launch_bounds__(256, 2) void build_H(const float* __restrict__ w3)
{
    __shared__ float Wi[32 * 132];
    __shared__ float Wj[32 * 132];
    const int t = threadIdx.x;
    const int tx = t & 15, ty = t >> 4;
    const int ib = blockIdx.x * 128, jb = blockIdx.y * 128, b = blockIdx.z;
    const float* zr = g_zvar + b * 64;

    float acc[8][8];
#pragma unroll
    for (int r = 0; r < 8; r++)
#pragma unroll
        for (int c = 0; c < 8; c++) acc[r][c] = 0.f;

    for (int lc = 0; lc < 64; lc += 32) {
#pragma unroll
        for (int q = 0; q < 4; q++) {
            int f = t + q * 256;         // [0,1024)
            int row = f >> 3, c4 = f & 7;
            int l = lc + c4 * 4;
            float4 vi = *reinterpret_cast<const float4*>(w3 + (size_t)(ib + row) * 64 + l);
            Wi[(c4 * 4 + 0) * 132 + row] = vi.x;
            Wi[(c4 * 4 + 1) * 132 + row] = vi.y;
            Wi[(c4 * 4 + 2) * 132 + row] = vi.z;
            Wi[(c4 * 4 + 3) * 132 + row] = vi.w;
            float4 vj = *reinterpret_cast<const float4*>(w3 + (size_t)(jb + row) * 64 + l);
            Wj[(c4 * 4 + 0) * 132 + row] = vj.x * zr[l + 0];
            Wj[(c4 * 4 + 1) * 132 + row] = vj.y * zr[l + 1];
            Wj[(c4 * 4 + 2) * 132 + row] = vj.z * zr[l + 2];
            Wj[(c4 * 4 + 3) * 132 + row] = vj.w * zr[l + 3];
        }
        __syncthreads();
#pragma unroll
        for (int l = 0; l < 32; l++) {
            float a[8], bb[8];
            *reinterpret_cast<float4*>(a)      = *reinterpret_cast<const float4*>(&Wi[l * 132 + ty * 8]);
            *reinterpret_cast<float4*>(a + 4)  = *reinterpret_cast<const float4*>(&Wi[l * 132 + ty * 8 + 4]);
            *reinterpret_cast<float4*>(bb)     = *reinterpret_cast<const float4*>(&Wj[l * 132 + tx * 8]);
            *reinterpret_cast<float4*>(bb + 4) = *reinterpret_cast<const float4*>(&Wj[l * 132 + tx * 8 + 4]);
#pragma unroll
            for (int r = 0; r < 8; r++)
#pragma unroll
                for (int c = 0; c < 8; c++) acc[r][c] += a[r] * bb[c];
        }
        __syncthreads();
    }

    // epilogue: elementwise moment transform
    float a1i[8], a2i[8], a3i[8], vi[8];
    float a1j[8], a2j[8], a3j[8], vj[8];
#pragma unroll
    for (int r = 0; r < 8; r++) {
        int ig = b * 512 + ib + ty * 8 + r;
        a1i[r] = g_a1[ig]; a2i[r] = g_a2[ig]; a3i[r] = g_a3[ig]; vi[r] = g_v[ig];
    }
#pragma unroll
    for (int c = 0; c < 8; c++) {
        int jg = b * 512 + jb + tx * 8 + c;
        a1j[c] = g_a1[jg]; a2j[c] = g_a2[jg]; a3j[c] = g_a3[jg]; vj[c] = g_v[jg];
    }
#pragma unroll
    for (int r = 0; r < 8; r++) {
        int ig = ib + ty * 8 + r;
#pragma unroll
        for (int c = 0; c < 8; c++) {
            int jg = jb + tx * 8 + c;
            float c0 = acc[r][c];
            if (ig == jg) c0 = fmaxf(c0, EPSC);
            float c2 = c0 * c0;
            float h = a1i[r] * a1j[c] * c0
                    + 2.f * a2i[r] * a2j[c] * c2
                    + a3i[r] * a3j[c] * (6.f * c2 * c0 + 9.f * vi[r] * vj[c] * c0);
            g_H[((size_t)b * 512 + ig) * 512 + jg] = h;
        }
    }
}

// ------------------- diag41[b,o] = w41[o,:] H[b] w41[o,:]^T --------------------
// Block: 128 o-rows of one batch, loops all 4 j-tiles internally (no atomics).
__global__ __launch_bounds__(256, 2) void bilinear_diag(const float* __restrict__ w41)
{
    __shared__ float As[16 * 132];
    __shared__ float Bs[16 * 128];
    const int t = threadIdx.x;
    const int tx = t & 15, ty = t >> 4;
    const int ob = blockIdx.x * 128;
    const int b  = blockIdx.y;
    const float* Hb = g_H + ((size_t)b << 18);

    float partD[8];
#pragma unroll
    for (int r = 0; r < 8; r++) partD[r] = 0.f;

    for (int jt = 0; jt < 4; jt++) {
        const int jb = jt * 128;
        float P[8][8];
#pragma unroll
        for (int r = 0; r < 8; r++)
#pragma unroll
            for (int c = 0; c < 8; c++) P[r][c] = 0.f;

        for (int kc = 0; kc < 512; kc += 16) {
#pragma unroll
            for (int q = 0; q < 2; q++) {           // A tile (w41): transpose to As[k][o]
                int f = t + q * 256;                 // [0,512)
                int row = f >> 2, c4 = f & 3;
                int og = ob + row;
                float4 v = make_float4(0.f, 0.f, 0.f, 0.f);
                if (og < 784) v = *reinterpret_cast<const float4*>(w41 + (size_t)og * 512 + kc + c4 * 4);
                As[(c4 * 4 + 0) * 132 + row] = v.x;
                As[(c4 * 4 + 1) * 132 + row] = v.y;
                As[(c4 * 4 + 2) * 132 + row] = v.z;
                As[(c4 * 4 + 3) * 132 + row] = v.w;
            }
#pragma unroll
            for (int q = 0; q < 2; q++) {           // B tile (H): direct
                int f = t + q * 256;
                int row = f >> 5, c4 = f & 31;
                float4 v = *reinterpret_cast<const float4*>(Hb + (size_t)(kc + row) * 512 + jb + c4 * 4);
                *reinterpret_cast<float4*>(&Bs[row * 128 + c4 * 4]) = v;
            }
            __syncthreads();
#pragma unroll
            for (int kk = 0; kk < 16; kk++) {
                float a[8], bb[8];
                *reinterpret_cast<float4*>(a)      = *reinterpret_cast<const float4*>(&As[kk * 132 + ty * 8]);
                *reinterpret_cast<float4*>(a + 4)  = *reinterpret_cast<const float4*>(&As[kk * 132 + ty * 8 + 4]);
                *reinterpret_cast<float4*>(bb)     = *reinterpret_cast<const float4*>(&Bs[kk * 128 + tx * 8]);
                *reinterpret_cast<float4*>(bb + 4) = *reinterpret_cast<const float4*>(&Bs[kk * 128 + tx * 8 + 4]);
#pragma unroll
                for (int r = 0; r < 8; r++)
#pragma unroll
                    for (int c = 0; c < 8; c++) P[r][c] += a[r] * bb[c];
            }
            __syncthreads();
        }

        // epilogue: multiply by w41[o, j] and accumulate row partials
#pragma unroll
        for (int r = 0; r < 8; r++) {
            int og = ob + ty * 8 + r;
            if (og < 784) {
                float4 u0 = *reinterpret_cast<const float4*>(w41 + (size_t)og * 512 + jb + tx * 8);
                float4 u1 = *reinterpret_cast<const float4*>(w41 + (size_t)og * 512 + jb + tx * 8 + 4);
                partD[r] += P[r][0] * u0.x + P[r][1] * u0.y + P[r][2] * u0.z + P[r][3] * u0.w
                          + P[r][4] * u1.x + P[r][5] * u1.y + P[r][6] * u1.z + P[r][7] * u1.w;
            }
        }
    }

    // cross-thread reduction over tx (16 partials per o), reuse As
    float* red = As;   // needs 2048 floats; As has 2112
#pragma unroll
    for (int r = 0; r < 8; r++) red[(ty * 8 + r) * 16 + tx] = partD[r];
    __syncthreads();
    if (t < 128) {
        float s = 0.f;
#pragma unroll
        for (int q = 0; q < 16; q++) s += red[t * 16 + q];
        int og = ob + t;
        if (og < 784) g_diag41[b * 784 + og] = s;
    }
}

// ------------------- probs: sigmoid A0 only ------------------------------------
__global__ void probs_kernel(float* __restrict__ out)
{
    int idx = blockIdx.x * blockDim.x + threadIdx.x;
    if (idx >= 64 * 784) return;
    float v = fmaxf(g_diag41[idx], EPSC);
    float m = g_m41[idx];
    float s = 0.f;
#pragma unroll
    for (int g = 0; g < 10; g++) {
        float gam = GS[g];
        float cg = 1.0f / (2.0f * gam * gam);
        float ivh = v + cg;
        s += 0.5f * (1.0f + erff(m / sqrtf(2.0f * ivh)));
    }
    out[idx] = s * 0.1f;
}

// ------------------- launcher --------------------------------------------------
extern "C" void kernel_launch(void* const* d_in, const int* in_sizes, int n_in,
                              void* d_out, int out_size)
{
    const float* x   = (const float*)d_in[0];
    const float* w1  = (const float*)d_in[1];
    const float* b1  = (const float*)d_in[2];
    const float* w21 = (const float*)d_in[3];
    const float* b21 = (const float*)d_in[4];
    const float* w22 = (const float*)d_in[5];
    const float* b22 = (const float*)d_in[6];
    const float* w3  = (const float*)d_in[7];
    const float* b3  = (const float*)d_in[8];
    const float* w41 = (const float*)d_in[9];
    const float* b41 = (const float*)d_in[10];
    float* out = (float*)d_out;

    float *h1, *zvar, *m3, *a0, *m41;
    cudaGetSymbolAddress((void**)&h1,   g_h1);
    cudaGetSymbolAddress((void**)&zvar, g_zvar);
    cudaGetSymbolAddress((void**)&m3,   g_m3);
    cudaGetSymbolAddress((void**)&a0,   g_a0);
    cudaGetSymbolAddress((void**)&m41,  g_m41);

    // h1 = tanh(x @ w1.T + b1)                       [64,512]
    gemm_bias_act<0><<<8, 256>>>(x, w1, b1, h1, 512, 784, nullptr);
    // z_mean -> out[0:4096]                          [64,64]
    gemm_bias_act<1><<<1, 256>>>(h1, w21, b21, out, 64, 512, nullptr);
    // z_logvar -> out[4096:8192], z_var -> scratch   [64,64]
    gemm_bias_act<2><<<1, 256>>>(h1, w22, b22, out + 64 * 64, 64, 512, zvar);
    // m3 = z_mean @ w3.T + b3                        [64,512]
    gemm_bias_act<1><<<8, 256>>>(out, w3, b3, m3, 512, 64, nullptr);
    // tanh moment coefficients + clipped diag
    moments_tanh<<<128, 256>>>(w3);
    // H = cov_h3 (fused cov3 construction + transform)
    build_H<<<dim3(4, 4, 64), 256>>>(w3);
    // m41 = a0 @ w41.T + b41                         [64,784]
    gemm_bias_act<1><<<13, 256>>>(a0, w41, b41, m41, 784, 512, nullptr);
    // diag of cov41 only (the key algebraic saving)
    bilinear_diag<<<dim3(7, 64), 256>>>(w41);
    // probs -> out[8192:]
    probs_kernel<<<(64 * 784 + 255) / 256, 256>>>(out + 2 * 64 * 64);
}